// round 2
// baseline (speedup 1.0000x reference)
#include <cuda_runtime.h>
#include <cstdint>

// Problem constants
#define E_LEN  512
#define NFEA   8
#define NCLS   14
#define BATCH  8192
#define ROW    (E_LEN * NFEA)        // 4096 floats per sample
#define NPAIR  (NCLS * NCLS)         // 196

#define GRID   152                   // GB300 has 152 SMs
#define TPB    256
#define WPB    (TPB / 32)            // 8 warps/block
#define NWARPS (GRID * WPB)          // 1216

typedef unsigned long long u64;

// Device scratch (no allocations allowed)
__device__ float g_gram[NPAIR];
__device__ float g_partial[NWARPS];

// ---- f32x2 helpers (ptxas will not auto-emit FFMA2 from C++) ----
__device__ __forceinline__ u64 pk2(float lo, float hi) {
    u64 r; asm("mov.b64 %0, {%1, %2};" : "=l"(r) : "f"(lo), "f"(hi)); return r;
}
__device__ __forceinline__ u64 bc2(float v) {
    u64 r; asm("mov.b64 %0, {%1, %1};" : "=l"(r) : "f"(v)); return r;
}
__device__ __forceinline__ u64 fma2(u64 a, u64 b, u64 c) {
    u64 d; asm("fma.rn.f32x2 %0, %1, %2, %3;" : "=l"(d) : "l"(a), "l"(b), "l"(c)); return d;
}
__device__ __forceinline__ u64 add2(u64 a, u64 b) {
    u64 d; asm("add.rn.f32x2 %0, %1, %2;" : "=l"(d) : "l"(a), "l"(b)); return d;
}

__device__ __forceinline__ float softplus_f(float v) {
    // log1p(exp(v)), numerically stable
    return fmaxf(v, 0.f) + log1pf(__expf(-fabsf(v)));
}

// Partitioned halving reduction stage: lanes with (lane & W) keep the upper
// half of their current index range; each stage halves per-lane data.
// After stages (32,16)(16,8)(8,4)(4,2)(2,1): lane l holds flat sums {2l, 2l+1}.
template<int H, int W>
__device__ __forceinline__ void red_stage(u64* v, int lane) {
    const bool up = (lane & W) != 0;
    #pragma unroll
    for (int i = 0; i < H; i++) {
        u64 send = up ? v[i] : v[i + H];
        u64 recv = __shfl_xor_sync(0xffffffffu, send, W);
        u64 keep = up ? v[i + H] : v[i];
        v[i] = add2(keep, recv);
    }
}

// ---------- Kernel 1: 14x14 Gram matrix of word vectors ----------
__global__ void gram_kernel(const float* __restrict__ w) {
    int c1 = blockIdx.x / NCLS, c2 = blockIdx.x % NCLS;
    int lane = threadIdx.x;
    float s = 0.f;
    for (int e = lane; e < E_LEN; e += 32)
        s += w[e * NCLS + c1] * w[e * NCLS + c2];
    #pragma unroll
    for (int o = 16; o; o >>= 1) s += __shfl_xor_sync(~0u, s, o);
    if (lane == 0) g_gram[blockIdx.x] = s;
}

// ---------- Kernel 2: main fused loss, warp-per-sample ----------
__global__ __launch_bounds__(TPB, 1)
void main_kernel(const float* __restrict__ x, const int* __restrict__ y,
                 const float* __restrict__ w) {
    // w packed as class-pairs, class-pair-major: s_w2[cc*512 + e] = (w[e][2cc], w[e][2cc+1])
    __shared__ u64   s_w2[7 * E_LEN];          // 28 KB
    __shared__ u64   s_red[WPB][64];           // 4 KB  (per-warp reduced accs)
    __shared__ float s_dot[WPB][NCLS];         // per-warp max-over-m dots
    __shared__ float s_G[NPAIR];

    const int tid = threadIdx.x;
    for (int idx = tid; idx < 7 * E_LEN; idx += TPB) {
        int e  = idx & (E_LEN - 1);
        int cc = idx >> 9;
        float2 wv = *(const float2*)(w + e * NCLS + cc * 2);  // even offset -> 8B aligned
        s_w2[cc * E_LEN + e] = pk2(wv.x, wv.y);
    }
    if (tid < NPAIR) s_G[tid] = g_gram[tid];
    __syncthreads();

    const int lane = tid & 31, wid = tid >> 5;
    const int gw = blockIdx.x * WPB + wid;
    float wacc = 0.f;

    for (int s = gw; s < BATCH; s += NWARPS) {
        const float4* px = (const float4*)(x + (size_t)s * ROW);

        // depth-2 software pipeline of the two float4 loads per e-iteration
        float4 a0 = __ldcs(px + lane * 2),        b0 = __ldcs(px + lane * 2 + 1);
        float4 a1 = __ldcs(px + (lane + 32) * 2), b1 = __ldcs(px + (lane + 32) * 2 + 1);

        u64 v[64];                                // flat index f = m*8 + cc (cc<7), cc==7 = pad
        #pragma unroll
        for (int f = 0; f < 64; f++) v[f] = 0ull;
        float l1 = 0.f;

        #pragma unroll
        for (int j = 0; j < 16; j++) {
            int jn = (j + 2 < 16) ? (j + 2) : 15;   // clamped prefetch index (stays in row)
            float4 a2 = __ldcs(px + (lane + 32 * jn) * 2);
            float4 b2 = __ldcs(px + (lane + 32 * jn) * 2 + 1);
            const int e = lane + 32 * j;

            // broadcast each un[e,m] into both f32x2 halves
            u64 bm[8] = { bc2(a0.x), bc2(a0.y), bc2(a0.z), bc2(a0.w),
                          bc2(b0.x), bc2(b0.y), bc2(b0.z), bc2(b0.w) };
            #pragma unroll
            for (int cc = 0; cc < 7; cc++) {
                u64 w2 = s_w2[cc * E_LEN + e];
                #pragma unroll
                for (int m = 0; m < 8; m++)
                    v[m * 8 + cc] = fma2(bm[m], w2, v[m * 8 + cc]);
            }

            // per-(b,e) unbiased variance over the 8 feature slots
            float s1 = ((a0.x + a0.y) + (a0.z + a0.w)) + ((b0.x + b0.y) + (b0.z + b0.w));
            float s2 = fmaf(a0.x, a0.x, fmaf(a0.y, a0.y, fmaf(a0.z, a0.z, fmaf(a0.w, a0.w,
                       fmaf(b0.x, b0.x, fmaf(b0.y, b0.y, fmaf(b0.z, b0.z, b0.w * b0.w)))))));
            float var = (s2 - s1 * s1 * 0.125f) * (1.0f / 7.0f);
            l1 += fabsf(var);

            a0 = a1; b0 = b1; a1 = a2; b1 = b2;
        }

        // partitioned reduction of 64 packed partials across the warp
        red_stage<32, 16>(v, lane);
        red_stage<16,  8>(v, lane);
        red_stage< 8,  4>(v, lane);
        red_stage< 4,  2>(v, lane);
        red_stage< 2,  1>(v, lane);
        s_red[wid][2 * lane]     = v[0];
        s_red[wid][2 * lane + 1] = v[1];
        __syncwarp();

        // dot[c] = max_m acc[m][c]
        if (lane < NCLS) {
            int cc = lane >> 1, hf = lane & 1;
            const float* rp = (const float*)&s_red[wid][0];
            float mx = rp[(0 * 8 + cc) * 2 + hf];
            #pragma unroll
            for (int m = 1; m < 8; m++) mx = fmaxf(mx, rp[(m * 8 + cc) * 2 + hf]);
            s_dot[wid][lane] = mx;
        }
        int yv = (lane < NCLS) ? __ldg(y + (size_t)s * NCLS + lane) : 0;
        unsigned mask = __ballot_sync(~0u, yv == 1);     // bits >= 14 are 0
        __syncwarp();

        // pairwise softplus + Gram sums, distributed over lanes
        float psum = 0.f, gs = 0.f, ds = 0.f;
        for (int idx = lane; idx < NPAIR; idx += 32) {
            int p = idx / NCLS, n = idx - p * NCLS;
            bool pp = (mask >> p) & 1, pn = (mask >> n) & 1;
            if (pp && !pn) psum += softplus_f(s_dot[wid][n] - s_dot[wid][p]);
            if (pp && pn) { float g = s_G[idx]; gs += g; if (p == n) ds += g; }
        }
        float li = l1;
        #pragma unroll
        for (int o = 16; o; o >>= 1) {
            psum += __shfl_xor_sync(~0u, psum, o);
            gs   += __shfl_xor_sync(~0u, gs,   o);
            ds   += __shfl_xor_sync(~0u, ds,   o);
            li   += __shfl_xor_sync(~0u, li,   o);
        }

        if (lane == 0) {
            float npos = (float)__popc(mask);
            float S = psum;
            if ((mask & 0x3FFFu) == 0x3FFFu) {   // nneg == 0 (can't happen with given data)
                S = 0.f;
                for (int c = 0; c < NCLS; c++) S += softplus_f(-s_dot[wid][c]);
            }
            float base = S / npos;
            // total_var via Gram identity: (sum diag - (sum all pos pairs)/npos)/(npos-1)
            float tv = (npos > 1.5f) ? (ds - gs / npos) / (npos - 1.f) : 0.f;
            float loss = 2.f * (0.7f * (1.f + tv) * base + 0.3f * li);
            wacc += loss;
        }
    }
    if (lane == 0) g_partial[gw] = wacc;
}

// ---------- Kernel 3: deterministic final reduction ----------
__global__ void final_kernel(float* __restrict__ out) {
    __shared__ float sh[TPB];
    int tid = threadIdx.x;
    float s = 0.f;
    for (int i = tid; i < NWARPS; i += TPB) s += g_partial[i];
    sh[tid] = s;
    __syncthreads();
    for (int o = TPB / 2; o; o >>= 1) {
        if (tid < o) sh[tid] += sh[tid + o];
        __syncthreads();
    }
    if (tid == 0) out[0] = sh[0] * (1.0f / (float)BATCH);
}

extern "C" void kernel_launch(void* const* d_in, const int* in_sizes, int n_in,
                              void* d_out, int out_size) {
    // Map inputs by element count (robust to ordering): x=33554432, y=114688, w=7168
    const float* x = nullptr; const int* y = nullptr; const float* w = nullptr;
    for (int i = 0; i < n_in; i++) {
        if      (in_sizes[i] == BATCH * ROW)   x = (const float*)d_in[i];
        else if (in_sizes[i] == BATCH * NCLS)  y = (const int*)d_in[i];
        else if (in_sizes[i] == E_LEN * NCLS)  w = (const float*)d_in[i];
    }
    gram_kernel<<<NPAIR, 32>>>(w);
    main_kernel<<<GRID, TPB>>>(x, y, w);
    final_kernel<<<1, TPB>>>((float*)d_out);
}

// round 7
// speedup vs baseline: 1.0324x; 1.0324x over previous
#include <cuda_runtime.h>
#include <cstdint>

// Problem constants
#define E_LEN  512
#define NFEA   8
#define NCLS   14
#define BATCH  8192
#define ROW    (E_LEN * NFEA)        // 4096 floats per sample
#define NPAIR  (NCLS * NCLS)         // 196

#define GRID   152                   // GB300: 152 SMs, 1 CTA each
#define TPB    512                   // 16 warps, 4/SMSP (128 regs max -> full RF)
#define WPB    (TPB / 32)
#define NWARPS (GRID * WPB)          // 2432

typedef unsigned long long u64;

__device__ float g_partial[NWARPS];

// ---- f32x2 helpers (ptxas never auto-emits FFMA2 from C++) ----
__device__ __forceinline__ u64 pk2(float lo, float hi) {
    u64 r; asm("mov.b64 %0, {%1, %2};" : "=l"(r) : "f"(lo), "f"(hi)); return r;
}
__device__ __forceinline__ void up2(float& lo, float& hi, u64 v) {
    asm("mov.b64 {%0, %1}, %2;" : "=f"(lo), "=f"(hi) : "l"(v));
}
__device__ __forceinline__ u64 bc2(float v) {
    u64 r; asm("mov.b64 %0, {%1, %1};" : "=l"(r) : "f"(v)); return r;
}
__device__ __forceinline__ u64 fma2(u64 a, u64 b, u64 c) {
    u64 d; asm("fma.rn.f32x2 %0, %1, %2, %3;" : "=l"(d) : "l"(a), "l"(b), "l"(c)); return d;
}
__device__ __forceinline__ u64 add2(u64 a, u64 b) {
    u64 d; asm("add.rn.f32x2 %0, %1, %2;" : "=l"(d) : "l"(a), "l"(b)); return d;
}

__device__ __forceinline__ float softplus_f(float v) {
    return fmaxf(v, 0.f) + log1pf(__expf(-fabsf(v)));
}

// Partitioned halving reduction stage among lanes sharing bit0 (masks 16,8,4,2).
// After all stages lane l holds flat elements {2*(l>>1), 2*(l>>1)+1} of its parity group.
template<int H, int W>
__device__ __forceinline__ void red_stage(u64* v, int lane) {
    const bool up = (lane & W) != 0;
    #pragma unroll
    for (int i = 0; i < H; i++) {
        u64 send = up ? v[i] : v[i + H];
        u64 recv = __shfl_xor_sync(0xffffffffu, send, W);
        u64 keep = up ? v[i + H] : v[i];
        v[i] = add2(keep, recv);
    }
}

// ---------- Fused main kernel (gram prologue + loss) ----------
__global__ __launch_bounds__(TPB, 1)
void main_kernel(const float* __restrict__ x, const int* __restrict__ y,
                 const float* __restrict__ w) {
    // w packed class-pair-major: s_w2[cc*512 + e] = (w[e][2cc], w[e][2cc+1])
    __shared__ u64   s_w2[7 * E_LEN];          // 28 KB
    __shared__ u64   s_red[WPB][64];           // 8 KB
    __shared__ float s_dot[WPB][NCLS];
    __shared__ float s_G[NPAIR];

    const int tid = threadIdx.x;
    const int lane = tid & 31, wid = tid >> 5;

    for (int idx = tid; idx < 7 * E_LEN; idx += TPB) {
        int e  = idx & (E_LEN - 1);
        int cc = idx >> 9;
        float2 wv = *(const float2*)(w + e * NCLS + cc * 2);  // 8B-aligned (even class)
        s_w2[cc * E_LEN + e] = pk2(wv.x, wv.y);
    }
    __syncthreads();

    // --- Gram prologue: 105 unique pairs, warp-per-pair, lanes split e ---
    {
        const float* wf = (const float*)s_w2;   // w[e][c] at (c>>1)*1024 + 2e + (c&1)
        for (int p = wid; p < 105; p += WPB) {
            int c1 = 0, rem = p;
            while (rem >= NCLS - c1) { rem -= NCLS - c1; c1++; }
            int c2 = c1 + rem;
            int o1 = (c1 >> 1) * 1024 + (c1 & 1);
            int o2 = (c2 >> 1) * 1024 + (c2 & 1);
            float s = 0.f;
            #pragma unroll
            for (int k = 0; k < 16; k++) {
                int e2 = 2 * (lane + 32 * k);
                s = fmaf(wf[o1 + e2], wf[o2 + e2], s);
            }
            #pragma unroll
            for (int o = 16; o; o >>= 1) s += __shfl_xor_sync(~0u, s, o);
            if (lane == 0) { s_G[c1 * NCLS + c2] = s; s_G[c2 * NCLS + c1] = s; }
        }
    }
    __syncthreads();

    // --- Main loop: warp per sample; lane pairs share e, split m 0-3 / 4-7 ---
    const int gw = wid * GRID + blockIdx.x;    // spreads the +1-sample warps across SMs
    float wacc = 0.f;

    for (int s = gw; s < BATCH; s += NWARPS) {
        const float4* px = (const float4*)(x + (size_t)s * ROW);

        // lane l reads float4 index 32*j + l  (16B per lane, coalesced)
        float4 c0 = __ldcs(px + lane);
        float4 c1 = __ldcs(px + 32 + lane);

        u64 v[32];                              // f = m_local*8 + cc (cc<7; 7 = pad)
        #pragma unroll
        for (int f = 0; f < 32; f++) v[f] = 0ull;
        float l1 = 0.f;

        #pragma unroll
        for (int j = 0; j < 32; j++) {
            int jn = (j + 2 < 32) ? (j + 2) : 31;
            float4 c2 = __ldcs(px + 32 * jn + lane);
            const int e = 16 * j + (lane >> 1);

            u64 b0v = bc2(c0.x), b1v = bc2(c0.y), b2v = bc2(c0.z), b3v = bc2(c0.w);
            #pragma unroll
            for (int cc = 0; cc < 7; cc++) {
                u64 w2 = s_w2[cc * E_LEN + e];
                v[0 * 8 + cc] = fma2(b0v, w2, v[0 * 8 + cc]);
                v[1 * 8 + cc] = fma2(b1v, w2, v[1 * 8 + cc]);
                v[2 * 8 + cc] = fma2(b2v, w2, v[2 * 8 + cc]);
                v[3 * 8 + cc] = fma2(b3v, w2, v[3 * 8 + cc]);
            }

            // per-(b,e) unbiased variance over 8 m: combine the two half-lane partials
            float p1 = (c0.x + c0.y) + (c0.z + c0.w);
            float p2 = fmaf(c0.x, c0.x, fmaf(c0.y, c0.y, fmaf(c0.z, c0.z, c0.w * c0.w)));
            u64 other = __shfl_xor_sync(~0u, pk2(p1, p2), 1);
            float q1, q2; up2(q1, q2, other);
            float s1 = p1 + q1, s2 = p2 + q2;
            float var = (s2 - s1 * s1 * 0.125f) * (1.0f / 7.0f);
            l1 += fabsf(var);                   // counted by BOTH parity lanes -> x0.5 later

            c0 = c1; c1 = c2;
        }

        // reduce 32 packed partials among lanes of same parity (masks 16,8,4,2)
        red_stage<16, 16>(v, lane);
        red_stage< 8,  8>(v, lane);
        red_stage< 4,  4>(v, lane);
        red_stage< 2,  2>(v, lane);
        s_red[wid][(lane & 1) * 32 + 2 * (lane >> 1)]     = v[0];
        s_red[wid][(lane & 1) * 32 + 2 * (lane >> 1) + 1] = v[1];
        __syncwarp();

        // dot[c] = max over m (m = 4*parity + m_local)
        if (lane < NCLS) {
            const float* rp = (const float*)&s_red[wid][0];
            int cc = lane >> 1, par = lane & 1;
            float mx = -3.4e38f;
            #pragma unroll
            for (int m = 0; m < 8; m++) {
                int h = m >> 2, ml = m & 3;
                mx = fmaxf(mx, rp[h * 64 + (ml * 8 + cc) * 2 + par]);
            }
            s_dot[wid][lane] = mx;
        }
        int yv = (lane < NCLS) ? __ldg(y + (size_t)s * NCLS + lane) : 0;
        unsigned mask = __ballot_sync(~0u, yv == 1);
        __syncwarp();

        // pairwise softplus + Gram sums, distributed over lanes
        float psum = 0.f, gs = 0.f, ds = 0.f;
        for (int idx = lane; idx < NPAIR; idx += 32) {
            int p = idx / NCLS, n = idx - p * NCLS;
            bool pp = (mask >> p) & 1, pn = (mask >> n) & 1;
            if (pp && !pn) psum += softplus_f(s_dot[wid][n] - s_dot[wid][p]);
            if (pp && pn) { float g = s_G[idx]; gs += g; if (p == n) ds += g; }
        }
        float li = l1;
        #pragma unroll
        for (int o = 16; o; o >>= 1) {
            psum += __shfl_xor_sync(~0u, psum, o);
            gs   += __shfl_xor_sync(~0u, gs,   o);
            ds   += __shfl_xor_sync(~0u, ds,   o);
            li   += __shfl_xor_sync(~0u, li,   o);
        }

        if (lane == 0) {
            float npos = (float)__popc(mask);
            float S = psum;
            if ((mask & 0x3FFFu) == 0x3FFFu) {  // nneg == 0 edge case
                S = 0.f;
                for (int c = 0; c < NCLS; c++) S += softplus_f(-s_dot[wid][c]);
            }
            float base = S / npos;
            float tv = (npos > 1.5f) ? (ds - gs / npos) / (npos - 1.f) : 0.f;
            float loss = 2.f * (0.7f * (1.f + tv) * base + 0.3f * (0.5f * li));
            wacc += loss;
        }
    }
    if (lane == 0) g_partial[gw] = wacc;
}

// ---------- Deterministic final reduction ----------
__global__ void final_kernel(float* __restrict__ out) {
    __shared__ float sh[256];
    int tid = threadIdx.x;
    float s = 0.f;
    for (int i = tid; i < NWARPS; i += 256) s += g_partial[i];
    sh[tid] = s;
    __syncthreads();
    for (int o = 128; o; o >>= 1) {
        if (tid < o) sh[tid] += sh[tid + o];
        __syncthreads();
    }
    if (tid == 0) out[0] = sh[0] * (1.0f / (float)BATCH);
}

extern "C" void kernel_launch(void* const* d_in, const int* in_sizes, int n_in,
                              void* d_out, int out_size) {
    const float* x = nullptr; const int* y = nullptr; const float* w = nullptr;
    for (int i = 0; i < n_in; i++) {
        if      (in_sizes[i] == BATCH * ROW)   x = (const float*)d_in[i];
        else if (in_sizes[i] == BATCH * NCLS)  y = (const int*)d_in[i];
        else if (in_sizes[i] == E_LEN * NCLS)  w = (const float*)d_in[i];
    }
    main_kernel<<<GRID, TPB>>>(x, y, w);
    final_kernel<<<1, 256>>>((float*)d_out);
}